// round 14
// baseline (speedup 1.0000x reference)
#include <cuda_runtime.h>
#include <cuda_fp16.h>
#include <math.h>
#include <stdint.h>

#define BB   4
#define HH   16
#define LL   2048
#define DD   1024
#define DH   64
#define MM   (BB*LL)   // 8192 tokens

// Scratch (device globals: allocation-free, graph-capturable). All fp16.
__device__ __half g_q[(size_t)BB*HH*LL*DH];    // (B,H,L,dh), pre-scaled by 0.125*log2e
__device__ __half g_k[(size_t)BB*HH*LL*DH];    // (B,H,Lc,dh) COMPACTED keys
__device__ __half g_v[(size_t)BB*HH*DH*LL];    // (B,H,dh,Lc) TRANSPOSED + COMPACTED
__device__ __half g_ctx[(size_t)MM*DD];        // (B,L,D)
__device__ __half g_xt[(size_t)MM*DD];         // x in fp16
__device__ __half g_wt[(size_t)4*DD*DD];       // wq,wk,wv,wo in fp16 (contiguous!)
__device__ int    g_cpos[(size_t)BB*LL];       // compact position or -1 if masked
__device__ int    g_cnt[BB];                   // unmasked count per batch

// ---------------- helpers ----------------
__device__ __forceinline__ void mma_f16(float c[4], const uint32_t a[4],
                                        uint32_t b0, uint32_t b1) {
    asm volatile(
        "mma.sync.aligned.m16n8k16.row.col.f32.f16.f16.f32 "
        "{%0,%1,%2,%3}, {%4,%5,%6,%7}, {%8,%9}, {%0,%1,%2,%3};"
        : "+f"(c[0]), "+f"(c[1]), "+f"(c[2]), "+f"(c[3])
        : "r"(a[0]), "r"(a[1]), "r"(a[2]), "r"(a[3]), "r"(b0), "r"(b1));
}
__device__ __forceinline__ void ldsm_x4(uint32_t r[4], uint32_t saddr) {
    asm volatile("ldmatrix.sync.aligned.m8n8.x4.shared.b16 {%0,%1,%2,%3}, [%4];"
                 : "=r"(r[0]), "=r"(r[1]), "=r"(r[2]), "=r"(r[3]) : "r"(saddr));
}
__device__ __forceinline__ void cp16(uint32_t saddr, const void* gptr) {
    asm volatile("cp.async.cg.shared.global [%0], [%1], 16;"
                 :: "r"(saddr), "l"(gptr));
}
#define CP_COMMIT() asm volatile("cp.async.commit_group;")
#define CP_WAIT1()  asm volatile("cp.async.wait_group 1;")
#define CP_WAIT2()  asm volatile("cp.async.wait_group 2;")

__device__ __forceinline__ uint32_t pack2(float a, float b) {
    __half2 h = __floats2half2_rn(a, b);
    return *reinterpret_cast<uint32_t*>(&h);
}
__device__ __forceinline__ float ex2(float x) {
    float r;
    asm("ex2.approx.f32 %0, %1;" : "=f"(r) : "f"(x));
    return r;
}
__device__ __forceinline__ uint32_t smem_u32(const void* p) {
    uint32_t a;
    asm("{ .reg .u64 t; cvta.to.shared.u64 t, %1; cvt.u32.u64 %0, t; }"
        : "=r"(a) : "l"(p));
    return a;
}

// ---------------------------------------------------------------------------
// Per-batch exclusive prefix scan of unmasked positions.
// One block per batch, 256 threads x 8 elements.
// ---------------------------------------------------------------------------
__global__ void __launch_bounds__(256) scan_kernel(const int* __restrict__ mask)
{
    __shared__ int warp_sums[8];
    const int b   = blockIdx.x;
    const int tid = threadIdx.x;
    const int* m  = mask + (size_t)b * LL;
    const int base = tid * 8;

    int v[8], s = 0;
    #pragma unroll
    for (int i = 0; i < 8; i++) { v[i] = (m[base + i] == 0); s += v[i]; }

    const int lane = tid & 31, wid = tid >> 5;
    int ps = s;
    #pragma unroll
    for (int off = 1; off < 32; off <<= 1) {
        int t = __shfl_up_sync(0xffffffffu, ps, off);
        if (lane >= off) ps += t;
    }
    if (lane == 31) warp_sums[wid] = ps;
    __syncthreads();
    if (tid == 0) {
        int acc = 0;
        #pragma unroll
        for (int w = 0; w < 8; w++) { int t = warp_sums[w]; warp_sums[w] = acc; acc += t; }
        g_cnt[b] = acc;
    }
    __syncthreads();

    int excl = warp_sums[wid] + ps - s;
    #pragma unroll
    for (int i = 0; i < 8; i++) {
        g_cpos[(size_t)b * LL + base + i] = v[i] ? excl : -1;
        excl += v[i];
    }
}

// ---------------------------------------------------------------------------
// Convert x and the 4 weights to fp16.
// ---------------------------------------------------------------------------
__global__ void __launch_bounds__(256) cvt_kernel(
    const float* __restrict__ x,
    const float* __restrict__ wq, const float* __restrict__ wk,
    const float* __restrict__ wv, const float* __restrict__ wo)
{
    const size_t NX = (size_t)MM * DD / 4;
    const size_t NW = (size_t)DD * DD / 4;
    size_t i = (size_t)blockIdx.x * blockDim.x + threadIdx.x;
    if (i >= NX + 4 * NW) return;
    const float* src;
    __half* dst;
    size_t off;
    if (i < NX) { src = x; dst = g_xt; off = i; }
    else {
        size_t j = i - NX;
        int w = (int)(j / NW);
        off = j % NW;
        src = (w == 0) ? wq : (w == 1) ? wk : (w == 2) ? wv : wo;
        dst = g_wt + (size_t)w * DD * DD;
    }
    float4 v = ((const float4*)src)[off];
    ((__half2*)dst)[off*2]   = __floats2half2_rn(v.x, v.y);
    ((__half2*)dst)[off*2+1] = __floats2half2_rn(v.z, v.w);
}

// ---------------------------------------------------------------------------
// fp16 GEMM (R12/R13 mainloop): 128x128 tile, 256 threads, BK=32, 4-stage
// cp.async ring, ldmatrix.x4, register double-buffered fragments.
// mode 0: MERGED QKV (N=3072): q scaled 0.125*log2e; K/V stored at COMPACTED
//         key positions (masked keys dropped); V also transposed (B,H,dh,Lc).
// mode 3: O projection (fp32 out).
// ---------------------------------------------------------------------------
#define GROW 20
#define GSTW (2*128*GROW)
#define GSTAGES 4
#define GEMM_SMEM (GSTAGES*GSTW*4)  // 81920 B -> 2 CTAs/SM

__global__ void __launch_bounds__(256, 2) gemm_f16(
    const float* __restrict__ bq_, const float* __restrict__ bk_,
    const float* __restrict__ bv_, float* __restrict__ Oext,
    int mode)
{
    const __half* A = (mode == 3) ? g_ctx : g_xt;
    const __half* W = (mode == 3) ? (g_wt + (size_t)3*DD*DD) : g_wt;

    extern __shared__ uint32_t sm[];

    const int tid  = threadIdx.x;
    const int wid  = tid >> 5;
    const int lane = tid & 31;
    const int gid  = lane >> 2;
    const int tig  = lane & 3;
    const int warp_m = (wid & 1) * 64;
    const int warp_n = (wid >> 1) * 32;
    const int bm = blockIdx.y * 128;
    const int bn = blockIdx.x * 128;

    const int lmat = tid >> 7;
    const int lrow = tid & 127;
    const __half* grow = lmat ? (W + (size_t)(bn + lrow) * DD)
                              : (A + (size_t)(bm + lrow) * DD);
    const uint32_t smb = smem_u32(sm);
    const uint32_t ldst = smb + (uint32_t)(lmat*128 + lrow) * GROW * 4;

    const int g  = lane >> 3;
    const int rr = lane & 7;
    const int a_row = warp_m + (g & 1) * 8 + rr;
    const int a_kw  = (g >> 1) * 4;
    const int b_row = 128 + warp_n + (g >> 1) * 8 + rr;
    const int b_kw  = (g & 1) * 4;
    const uint32_t a_off0 = (uint32_t)((a_row +  0)*GROW + a_kw)*4;
    const uint32_t a_off1 = (uint32_t)((a_row + 16)*GROW + a_kw)*4;
    const uint32_t a_off2 = (uint32_t)((a_row + 32)*GROW + a_kw)*4;
    const uint32_t a_off3 = (uint32_t)((a_row + 48)*GROW + a_kw)*4;
    const uint32_t b_off0 = (uint32_t)((b_row +  0)*GROW + b_kw)*4;
    const uint32_t b_off1 = (uint32_t)((b_row + 16)*GROW + b_kw)*4;

    float acc[4][4][4];
    #pragma unroll
    for (int mt = 0; mt < 4; mt++)
        #pragma unroll
        for (int nt = 0; nt < 4; nt++)
            #pragma unroll
            for (int r = 0; r < 4; r++) acc[mt][nt][r] = 0.f;

    uint32_t afr[2][4][4];
    uint32_t bfr[2][2][4];

    #define LOAD_FRAGS(set_, Ab_, ks_) do { \
        ldsm_x4(afr[set_][0], (Ab_) + a_off0 + (ks_)*32); \
        ldsm_x4(afr[set_][1], (Ab_) + a_off1 + (ks_)*32); \
        ldsm_x4(afr[set_][2], (Ab_) + a_off2 + (ks_)*32); \
        ldsm_x4(afr[set_][3], (Ab_) + a_off3 + (ks_)*32); \
        ldsm_x4(bfr[set_][0], (Ab_) + b_off0 + (ks_)*32); \
        ldsm_x4(bfr[set_][1], (Ab_) + b_off1 + (ks_)*32); \
    } while (0)

    #define MMA_SET(set_) do { \
        _Pragma("unroll") \
        for (int j_ = 0; j_ < 2; j_++) \
            _Pragma("unroll") \
            for (int mt_ = 0; mt_ < 4; mt_++) { \
                mma_f16(acc[mt_][2*j_],   afr[set_][mt_], bfr[set_][j_][0], bfr[set_][j_][1]); \
                mma_f16(acc[mt_][2*j_+1], afr[set_][mt_], bfr[set_][j_][2], bfr[set_][j_][3]); \
            } \
    } while (0)

    #define G_ISSUE(t_) do { \
        uint32_t d_ = ldst + (uint32_t)((t_) & 3) * (GSTW*4); \
        const __half* s_ = grow + (t_) * 32; \
        cp16(d_,      s_);      cp16(d_ + 16, s_ + 8); \
        cp16(d_ + 32, s_ + 16); cp16(d_ + 48, s_ + 24); \
    } while (0)

    G_ISSUE(0); CP_COMMIT();
    G_ISSUE(1); CP_COMMIT();
    CP_WAIT1();
    __syncthreads();
    LOAD_FRAGS(0, smb, 0);

    for (int i = 0; i < 32; i++) {
        const uint32_t Abi = smb + (uint32_t)(i & 3) * (GSTW*4);
        LOAD_FRAGS(1, Abi, 1);
        if (i + 2 < 32) G_ISSUE(i + 2);
        CP_COMMIT();
        MMA_SET(0);
        if (i + 1 < 32) {
            CP_WAIT1();
            __syncthreads();
            const uint32_t Abn = smb + (uint32_t)((i+1) & 3) * (GSTW*4);
            LOAD_FRAGS(0, Abn, 0);
        }
        MMA_SET(1);
    }
    #undef G_ISSUE
    #undef LOAD_FRAGS
    #undef MMA_SET

    // epilogue
    const int which = (mode == 3) ? 3 : (bn >> 10);
    const float* bias = (which == 0) ? bq_ : (which == 1) ? bk_ : bv_;
    const float sc = (which == 0) ? 0.125f * 1.4426950408889634f : 1.f;

    #pragma unroll
    for (int mt = 0; mt < 4; mt++) {
        #pragma unroll
        for (int nt = 0; nt < 4; nt++) {
            const int col = bn + warp_n + nt*8 + tig*2;
            const int lc  = col & 1023;
            const float b0 = (mode == 3) ? bq_[lc] : bias[lc];
            const float b1 = (mode == 3) ? bq_[lc+1] : bias[lc+1];
            #pragma unroll
            for (int half_ = 0; half_ < 2; half_++) {
                const int m = bm + warp_m + mt*16 + gid + half_*8;
                float vx = (acc[mt][nt][half_*2 + 0] + b0) * sc;
                float vy = (acc[mt][nt][half_*2 + 1] + b1) * sc;
                if (mode == 3) {
                    *(float2*)&Oext[(size_t)m * DD + lc] = make_float2(vx, vy);
                } else {
                    const int bb = m >> 11;
                    const int ll = m & (LL - 1);
                    const int h  = lc >> 6;
                    const int c  = lc & (DH - 1);
                    if (which == 0) {
                        *(uint32_t*)&g_q[(((size_t)(bb*HH + h)*LL) + ll)*DH + c] =
                            pack2(vx, vy);
                    } else {
                        const int cp = g_cpos[(size_t)bb*LL + ll];
                        if (cp >= 0) {
                            if (which == 2) {   // V transposed+compacted (B,H,dh,Lc)
                                const size_t base = ((size_t)(bb*HH + h)) * DH * LL;
                                g_v[base + (size_t)c    *LL + cp] = __float2half_rn(vx);
                                g_v[base + (size_t)(c+1)*LL + cp] = __float2half_rn(vy);
                            } else {            // K compacted
                                *(uint32_t*)&g_k[(((size_t)(bb*HH + h)*LL) + cp)*DH + c] =
                                    pack2(vx, vy);
                            }
                        }
                    }
                }
            }
        }
    }
}

// ---------------------------------------------------------------------------
// fp16 flash attention on COMPACTED keys: 128-query tile, 256 threads,
// nkt = ceil(cnt/64) key tiles (data-dependent, ~16). K/V 4-slot ring
// (prefetch distance 2), 1 CTA barrier per key tile. Q fragments register-
// resident; P never touches smem; softmax in log2 domain (ex2).
// Tail masking is positional: compact key index >= cnt -> -1e9.
// smem: Q 128x36 + K 4x64x36 + V 4x64x36 = 92160 B -> 2 CTAs/SM.
// ---------------------------------------------------------------------------
#define AQ_OFF 0
#define AK_OFF (128*36)
#define AV_OFF (AK_OFF + 4*64*36)
#define ATTN_SMEM ((AV_OFF + 4*64*36)*4)

__global__ void __launch_bounds__(256, 2) attn_f16()
{
    extern __shared__ uint32_t sm[];

    const int qt  = blockIdx.x;
    const int h   = blockIdx.y;
    const int b   = blockIdx.z;
    const int tid = threadIdx.x;
    const int wid = tid >> 5;
    const int lane = tid & 31;
    const int gid = lane >> 2;
    const int tig = lane & 3;
    const int m0  = wid * 16;

    const __half* qb = g_q + ((size_t)(b*HH + h))*LL*DH + (size_t)qt*128*DH;
    const __half* kb = g_k + ((size_t)(b*HH + h))*LL*DH;
    const __half* vb = g_v + ((size_t)(b*HH + h))*DH*LL;
    const uint32_t smb = smem_u32(sm);

    const int cnt = g_cnt[b];
    const int nkt = (cnt + 63) >> 6;

    const int g  = lane >> 3;
    const int rr = lane & 7;
    const int a_row = (g & 1) * 8 + rr;
    const int a_kw  = (g >> 1) * 4;
    const int b_row = (g >> 1) * 8 + rr;
    const int b_kw  = (g & 1) * 4;

    #define A_ISSUE(kt_) do { \
        const int tb_ = (kt_) & 3; \
        const __half* ksrc_ = kb + (size_t)(kt_)*64*DH; \
        _Pragma("unroll") \
        for (int rep_ = 0; rep_ < 2; rep_++) { \
            int idx_ = rep_*256 + tid; \
            int r_ = idx_ >> 3, w_ = (idx_ & 7); \
            cp16(smb + (uint32_t)(AK_OFF + tb_*64*36 + r_*36 + w_*4)*4, \
                 ksrc_ + (size_t)r_*DH + w_*8); \
            cp16(smb + (uint32_t)(AV_OFF + tb_*64*36 + r_*36 + w_*4)*4, \
                 vb + (size_t)r_*LL + (kt_)*64 + w_*8); \
        } \
    } while (0)

    // prologue: Q + tile 0 in group 0; tile 1 in group 1
    #pragma unroll
    for (int rep = 0; rep < 4; rep++) {
        int idx = rep*256 + tid;
        int r = idx >> 3, w = idx & 7;
        cp16(smb + (uint32_t)(AQ_OFF + r*36 + w*4)*4, qb + (size_t)r*DH + w*8);
    }
    A_ISSUE(0);
    CP_COMMIT();
    A_ISSUE(1);
    CP_COMMIT();

    float accO[8][4];
    #pragma unroll
    for (int nt = 0; nt < 8; nt++)
        #pragma unroll
        for (int r = 0; r < 4; r++) accO[nt][r] = 0.f;
    float mi[2] = {-INFINITY, -INFINITY};
    float li[2] = {0.f, 0.f};

    uint32_t qf[4][4];   // register-resident Q fragments

    for (int kt = 0; kt < nkt; kt++) {
        const int tb = kt & 3;

        if (kt + 2 < nkt) A_ISSUE(kt + 2);
        CP_COMMIT();
        CP_WAIT2();
        __syncthreads();

        if (kt == 0) {
            const uint32_t Qb = smb + (uint32_t)(AQ_OFF + (m0 + a_row)*36)*4;
            #pragma unroll
            for (int ks = 0; ks < 4; ks++)
                ldsm_x4(qf[ks], Qb + (uint32_t)(ks*8 + a_kw)*4);
        }

        // S = Q K^T  (Q pre-scaled by 0.125*log2e)
        float s[8][4];
        #pragma unroll
        for (int nt = 0; nt < 8; nt++)
            #pragma unroll
            for (int r = 0; r < 4; r++) s[nt][r] = 0.f;

        const uint32_t Kb = smb + (uint32_t)(AK_OFF + tb*64*36)*4;
        #pragma unroll
        for (int ks = 0; ks < 4; ks++) {
            const int kb8 = ks * 8;
            #pragma unroll
            for (int j = 0; j < 4; j++) {
                uint32_t bf[4];
                ldsm_x4(bf, Kb + (uint32_t)((j*16 + b_row)*36 + kb8 + b_kw)*4);
                mma_f16(s[2*j],   qf[ks], bf[0], bf[1]);
                mma_f16(s[2*j+1], qf[ks], bf[2], bf[3]);
            }
        }

        // positional tail mask: compact key index >= cnt
        #pragma unroll
        for (int nt = 0; nt < 8; nt++) {
            const int c0 = kt*64 + nt*8 + tig*2;
            if (c0     >= cnt) { s[nt][0] = -1e9f; s[nt][2] = -1e9f; }
            if (c0 + 1 >= cnt) { s[nt][1] = -1e9f; s[nt][3] = -1e9f; }
        }

        // online softmax in log2 domain (rows gid, gid+8)
        #pragma unroll
        for (int half_ = 0; half_ < 2; half_++) {
            float rm = -INFINITY;
            #pragma unroll
            for (int nt = 0; nt < 8; nt++)
                rm = fmaxf(rm, fmaxf(s[nt][half_*2], s[nt][half_*2+1]));
            rm = fmaxf(rm, __shfl_xor_sync(0xffffffffu, rm, 1));
            rm = fmaxf(rm, __shfl_xor_sync(0xffffffffu, rm, 2));
            const float newm = fmaxf(mi[half_], rm);
            const float corr = ex2(mi[half_] - newm);
            float rs = 0.f;
            #pragma unroll
            for (int nt = 0; nt < 8; nt++) {
                s[nt][half_*2]   = ex2(s[nt][half_*2]   - newm);
                s[nt][half_*2+1] = ex2(s[nt][half_*2+1] - newm);
                rs += s[nt][half_*2] + s[nt][half_*2+1];
            }
            rs += __shfl_xor_sync(0xffffffffu, rs, 1);
            rs += __shfl_xor_sync(0xffffffffu, rs, 2);
            li[half_] = li[half_] * corr + rs;
            mi[half_] = newm;
            #pragma unroll
            for (int nt = 0; nt < 8; nt++) {
                accO[nt][half_*2]   *= corr;
                accO[nt][half_*2+1] *= corr;
            }
        }

        // O += P @ V — P built directly from S fragments
        const uint32_t Vb = smb + (uint32_t)(AV_OFF + tb*64*36)*4;
        #pragma unroll
        for (int ks = 0; ks < 4; ks++) {
            const int kb8 = ks * 8;
            uint32_t af[4];
            af[0] = pack2(s[2*ks  ][0], s[2*ks  ][1]);
            af[1] = pack2(s[2*ks  ][2], s[2*ks  ][3]);
            af[2] = pack2(s[2*ks+1][0], s[2*ks+1][1]);
            af[3] = pack2(s[2*ks+1][2], s[2*ks+1][3]);
            #pragma unroll
            for (int j = 0; j < 4; j++) {
                uint32_t bf[4];
                ldsm_x4(bf, Vb + (uint32_t)((j*16 + b_row)*36 + kb8 + b_kw)*4);
                mma_f16(accO[2*j],   af, bf[0], bf[1]);
                mma_f16(accO[2*j+1], af, bf[2], bf[3]);
            }
        }
    }
    #undef A_ISSUE

    const float inv0 = 1.f / li[0];
    const float inv1 = 1.f / li[1];
    const int r0 = qt*128 + m0 + gid;
    const int r1 = r0 + 8;
    #pragma unroll
    for (int nt = 0; nt < 8; nt++) {
        const int c = h*DH + nt*8 + tig*2;
        *(uint32_t*)&g_ctx[((size_t)(b*LL + r0))*DD + c] =
            pack2(accO[nt][0]*inv0, accO[nt][1]*inv0);
        *(uint32_t*)&g_ctx[((size_t)(b*LL + r1))*DD + c] =
            pack2(accO[nt][2]*inv1, accO[nt][3]*inv1);
    }
}

// ---------------------------------------------------------------------------
extern "C" void kernel_launch(void* const* d_in, const int* in_sizes, int n_in,
                              void* d_out, int out_size)
{
    const float* x  = (const float*)d_in[0];
    const int* mask = (const int*)d_in[1];
    const float* wq = (const float*)d_in[2];
    const float* bq = (const float*)d_in[3];
    const float* wk = (const float*)d_in[4];
    const float* bk = (const float*)d_in[5];
    const float* wv = (const float*)d_in[6];
    const float* bv = (const float*)d_in[7];
    const float* wo = (const float*)d_in[8];
    const float* bo = (const float*)d_in[9];
    float* out = (float*)d_out;

    cudaFuncSetAttribute(gemm_f16, cudaFuncAttributeMaxDynamicSharedMemorySize,
                         GEMM_SMEM);
    cudaFuncSetAttribute(attn_f16, cudaFuncAttributeMaxDynamicSharedMemorySize,
                         ATTN_SMEM);

    scan_kernel<<<BB, 256>>>(mask);

    const int ncvt = (int)(((size_t)MM*DD/4 + (size_t)DD*DD + 255) / 256);
    cvt_kernel<<<ncvt, 256>>>(x, wq, wk, wv, wo);

    // merged QKV: N = 3072
    dim3 gqkv(3*DD/128, MM/128);   // 24 x 64 blocks
    gemm_f16<<<gqkv, 256, GEMM_SMEM>>>(bq, bk, bv, nullptr, 0);

    dim3 ga(LL/128, HH, BB);       // 16 x 16 x 4 blocks
    attn_f16<<<ga, 256, ATTN_SMEM>>>();

    dim3 go(DD/128, MM/128);       // 8 x 64 blocks
    gemm_f16<<<go, 256, GEMM_SMEM>>>(bo, nullptr, nullptr, out, 3);
}

// round 15
// speedup vs baseline: 1.5338x; 1.5338x over previous
#include <cuda_runtime.h>
#include <cuda_fp16.h>
#include <math.h>
#include <stdint.h>

#define BB   4
#define HH   16
#define LL   2048
#define DD   1024
#define DH   64
#define MM   (BB*LL)   // 8192 tokens

// Scratch (device globals: allocation-free, graph-capturable). All fp16.
__device__ __half g_q[(size_t)BB*HH*LL*DH];    // (B,H,L,dh), pre-scaled by 0.125*log2e
__device__ __half g_k[(size_t)BB*HH*LL*DH];    // (B,H,Lc,dh) COMPACTED keys
__device__ __half g_v[(size_t)BB*HH*DH*LL];    // (B,H,dh,Lc) TRANSPOSED + COMPACTED
__device__ __half g_ctx[(size_t)MM*DD];        // (B,L,D)
__device__ __half g_xt[(size_t)MM*DD];         // x in fp16
__device__ __half g_wt[(size_t)4*DD*DD];       // wq,wk,wv,wo in fp16 (contiguous!)
__device__ int    g_cpos[(size_t)BB*LL];       // compact position or -1 if masked
__device__ int    g_cnt[BB];                   // unmasked count per batch

// ---------------- helpers ----------------
__device__ __forceinline__ void mma_f16(float c[4], const uint32_t a[4],
                                        uint32_t b0, uint32_t b1) {
    asm volatile(
        "mma.sync.aligned.m16n8k16.row.col.f32.f16.f16.f32 "
        "{%0,%1,%2,%3}, {%4,%5,%6,%7}, {%8,%9}, {%0,%1,%2,%3};"
        : "+f"(c[0]), "+f"(c[1]), "+f"(c[2]), "+f"(c[3])
        : "r"(a[0]), "r"(a[1]), "r"(a[2]), "r"(a[3]), "r"(b0), "r"(b1));
}
__device__ __forceinline__ void ldsm_x4(uint32_t r[4], uint32_t saddr) {
    asm volatile("ldmatrix.sync.aligned.m8n8.x4.shared.b16 {%0,%1,%2,%3}, [%4];"
                 : "=r"(r[0]), "=r"(r[1]), "=r"(r[2]), "=r"(r[3]) : "r"(saddr));
}
__device__ __forceinline__ void cp16(uint32_t saddr, const void* gptr) {
    asm volatile("cp.async.cg.shared.global [%0], [%1], 16;"
                 :: "r"(saddr), "l"(gptr));
}
#define CP_COMMIT() asm volatile("cp.async.commit_group;")
#define CP_WAIT1()  asm volatile("cp.async.wait_group 1;")
#define CP_WAIT2()  asm volatile("cp.async.wait_group 2;")

__device__ __forceinline__ uint32_t pack2(float a, float b) {
    __half2 h = __floats2half2_rn(a, b);
    return *reinterpret_cast<uint32_t*>(&h);
}
__device__ __forceinline__ float ex2(float x) {
    float r;
    asm("ex2.approx.f32 %0, %1;" : "=f"(r) : "f"(x));
    return r;
}
__device__ __forceinline__ uint32_t smem_u32(const void* p) {
    uint32_t a;
    asm("{ .reg .u64 t; cvta.to.shared.u64 t, %1; cvt.u32.u64 %0, t; }"
        : "=r"(a) : "l"(p));
    return a;
}

// ---------------------------------------------------------------------------
// Per-batch exclusive prefix scan of unmasked positions.
// One block per batch, 256 threads x 8 elements.
// ---------------------------------------------------------------------------
__global__ void __launch_bounds__(256) scan_kernel(const int* __restrict__ mask)
{
    __shared__ int warp_sums[8];
    const int b   = blockIdx.x;
    const int tid = threadIdx.x;
    const int* m  = mask + (size_t)b * LL;
    const int base = tid * 8;

    int v[8], s = 0;
    #pragma unroll
    for (int i = 0; i < 8; i++) { v[i] = (m[base + i] == 0); s += v[i]; }

    const int lane = tid & 31, wid = tid >> 5;
    int ps = s;
    #pragma unroll
    for (int off = 1; off < 32; off <<= 1) {
        int t = __shfl_up_sync(0xffffffffu, ps, off);
        if (lane >= off) ps += t;
    }
    if (lane == 31) warp_sums[wid] = ps;
    __syncthreads();
    if (tid == 0) {
        int acc = 0;
        #pragma unroll
        for (int w = 0; w < 8; w++) { int t = warp_sums[w]; warp_sums[w] = acc; acc += t; }
        g_cnt[b] = acc;
    }
    __syncthreads();

    int excl = warp_sums[wid] + ps - s;
    #pragma unroll
    for (int i = 0; i < 8; i++) {
        g_cpos[(size_t)b * LL + base + i] = v[i] ? excl : -1;
        excl += v[i];
    }
}

// ---------------------------------------------------------------------------
// Convert x and the 4 weights to fp16.
// ---------------------------------------------------------------------------
__global__ void __launch_bounds__(256) cvt_kernel(
    const float* __restrict__ x,
    const float* __restrict__ wq, const float* __restrict__ wk,
    const float* __restrict__ wv, const float* __restrict__ wo)
{
    const size_t NX = (size_t)MM * DD / 4;
    const size_t NW = (size_t)DD * DD / 4;
    size_t i = (size_t)blockIdx.x * blockDim.x + threadIdx.x;
    if (i >= NX + 4 * NW) return;
    const float* src;
    __half* dst;
    size_t off;
    if (i < NX) { src = x; dst = g_xt; off = i; }
    else {
        size_t j = i - NX;
        int w = (int)(j / NW);
        off = j % NW;
        src = (w == 0) ? wq : (w == 1) ? wk : (w == 2) ? wv : wo;
        dst = g_wt + (size_t)w * DD * DD;
    }
    float4 v = ((const float4*)src)[off];
    ((__half2*)dst)[off*2]   = __floats2half2_rn(v.x, v.y);
    ((__half2*)dst)[off*2+1] = __floats2half2_rn(v.z, v.w);
}

// ---------------------------------------------------------------------------
// fp16 GEMM (R12/R13 mainloop): 128x128 tile, 256 threads, BK=32, 4-stage
// cp.async ring, ldmatrix.x4, register double-buffered fragments.
// mode 0: MERGED QKV (N=3072): q scaled 0.125*log2e; K/V stored at COMPACTED
//         key positions (masked keys dropped); V also transposed (B,H,dh,Lc).
// mode 3: O projection (fp32 out).
// ---------------------------------------------------------------------------
#define GROW 20
#define GSTW (2*128*GROW)
#define GSTAGES 4
#define GEMM_SMEM (GSTAGES*GSTW*4)  // 81920 B -> 2 CTAs/SM

__global__ void __launch_bounds__(256, 2) gemm_f16(
    const float* __restrict__ bq_, const float* __restrict__ bk_,
    const float* __restrict__ bv_, float* __restrict__ Oext,
    int mode)
{
    const __half* A = (mode == 3) ? g_ctx : g_xt;
    const __half* W = (mode == 3) ? (g_wt + (size_t)3*DD*DD) : g_wt;

    extern __shared__ uint32_t sm[];

    const int tid  = threadIdx.x;
    const int wid  = tid >> 5;
    const int lane = tid & 31;
    const int gid  = lane >> 2;
    const int tig  = lane & 3;
    const int warp_m = (wid & 1) * 64;
    const int warp_n = (wid >> 1) * 32;
    const int bm = blockIdx.y * 128;
    const int bn = blockIdx.x * 128;

    const int lmat = tid >> 7;
    const int lrow = tid & 127;
    const __half* grow = lmat ? (W + (size_t)(bn + lrow) * DD)
                              : (A + (size_t)(bm + lrow) * DD);
    const uint32_t smb = smem_u32(sm);
    const uint32_t ldst = smb + (uint32_t)(lmat*128 + lrow) * GROW * 4;

    const int g  = lane >> 3;
    const int rr = lane & 7;
    const int a_row = warp_m + (g & 1) * 8 + rr;
    const int a_kw  = (g >> 1) * 4;
    const int b_row = 128 + warp_n + (g >> 1) * 8 + rr;
    const int b_kw  = (g & 1) * 4;
    const uint32_t a_off0 = (uint32_t)((a_row +  0)*GROW + a_kw)*4;
    const uint32_t a_off1 = (uint32_t)((a_row + 16)*GROW + a_kw)*4;
    const uint32_t a_off2 = (uint32_t)((a_row + 32)*GROW + a_kw)*4;
    const uint32_t a_off3 = (uint32_t)((a_row + 48)*GROW + a_kw)*4;
    const uint32_t b_off0 = (uint32_t)((b_row +  0)*GROW + b_kw)*4;
    const uint32_t b_off1 = (uint32_t)((b_row + 16)*GROW + b_kw)*4;

    float acc[4][4][4];
    #pragma unroll
    for (int mt = 0; mt < 4; mt++)
        #pragma unroll
        for (int nt = 0; nt < 4; nt++)
            #pragma unroll
            for (int r = 0; r < 4; r++) acc[mt][nt][r] = 0.f;

    uint32_t afr[2][4][4];
    uint32_t bfr[2][2][4];

    #define LOAD_FRAGS(set_, Ab_, ks_) do { \
        ldsm_x4(afr[set_][0], (Ab_) + a_off0 + (ks_)*32); \
        ldsm_x4(afr[set_][1], (Ab_) + a_off1 + (ks_)*32); \
        ldsm_x4(afr[set_][2], (Ab_) + a_off2 + (ks_)*32); \
        ldsm_x4(afr[set_][3], (Ab_) + a_off3 + (ks_)*32); \
        ldsm_x4(bfr[set_][0], (Ab_) + b_off0 + (ks_)*32); \
        ldsm_x4(bfr[set_][1], (Ab_) + b_off1 + (ks_)*32); \
    } while (0)

    #define MMA_SET(set_) do { \
        _Pragma("unroll") \
        for (int j_ = 0; j_ < 2; j_++) \
            _Pragma("unroll") \
            for (int mt_ = 0; mt_ < 4; mt_++) { \
                mma_f16(acc[mt_][2*j_],   afr[set_][mt_], bfr[set_][j_][0], bfr[set_][j_][1]); \
                mma_f16(acc[mt_][2*j_+1], afr[set_][mt_], bfr[set_][j_][2], bfr[set_][j_][3]); \
            } \
    } while (0)

    #define G_ISSUE(t_) do { \
        uint32_t d_ = ldst + (uint32_t)((t_) & 3) * (GSTW*4); \
        const __half* s_ = grow + (t_) * 32; \
        cp16(d_,      s_);      cp16(d_ + 16, s_ + 8); \
        cp16(d_ + 32, s_ + 16); cp16(d_ + 48, s_ + 24); \
    } while (0)

    G_ISSUE(0); CP_COMMIT();
    G_ISSUE(1); CP_COMMIT();
    CP_WAIT1();
    __syncthreads();
    LOAD_FRAGS(0, smb, 0);

    for (int i = 0; i < 32; i++) {
        const uint32_t Abi = smb + (uint32_t)(i & 3) * (GSTW*4);
        LOAD_FRAGS(1, Abi, 1);
        if (i + 2 < 32) G_ISSUE(i + 2);
        CP_COMMIT();
        MMA_SET(0);
        if (i + 1 < 32) {
            CP_WAIT1();
            __syncthreads();
            const uint32_t Abn = smb + (uint32_t)((i+1) & 3) * (GSTW*4);
            LOAD_FRAGS(0, Abn, 0);
        }
        MMA_SET(1);
    }
    #undef G_ISSUE
    #undef LOAD_FRAGS
    #undef MMA_SET

    // epilogue
    const int which = (mode == 3) ? 3 : (bn >> 10);
    const float* bias = (which == 0) ? bq_ : (which == 1) ? bk_ : bv_;
    const float sc = (which == 0) ? 0.125f * 1.4426950408889634f : 1.f;

    #pragma unroll
    for (int mt = 0; mt < 4; mt++) {
        #pragma unroll
        for (int nt = 0; nt < 4; nt++) {
            const int col = bn + warp_n + nt*8 + tig*2;
            const int lc  = col & 1023;
            const float b0 = (mode == 3) ? bq_[lc] : bias[lc];
            const float b1 = (mode == 3) ? bq_[lc+1] : bias[lc+1];
            #pragma unroll
            for (int half_ = 0; half_ < 2; half_++) {
                const int m = bm + warp_m + mt*16 + gid + half_*8;
                float vx = (acc[mt][nt][half_*2 + 0] + b0) * sc;
                float vy = (acc[mt][nt][half_*2 + 1] + b1) * sc;
                if (mode == 3) {
                    *(float2*)&Oext[(size_t)m * DD + lc] = make_float2(vx, vy);
                } else {
                    const int bb = m >> 11;
                    const int ll = m & (LL - 1);
                    const int h  = lc >> 6;
                    const int c  = lc & (DH - 1);
                    if (which == 0) {
                        *(uint32_t*)&g_q[(((size_t)(bb*HH + h)*LL) + ll)*DH + c] =
                            pack2(vx, vy);
                    } else {
                        const int cp = g_cpos[(size_t)bb*LL + ll];
                        if (cp >= 0) {
                            if (which == 2) {   // V transposed+compacted (B,H,dh,Lc)
                                const size_t base = ((size_t)(bb*HH + h)) * DH * LL;
                                g_v[base + (size_t)c    *LL + cp] = __float2half_rn(vx);
                                g_v[base + (size_t)(c+1)*LL + cp] = __float2half_rn(vy);
                            } else {            // K compacted
                                *(uint32_t*)&g_k[(((size_t)(bb*HH + h)*LL) + cp)*DH + c] =
                                    pack2(vx, vy);
                            }
                        }
                    }
                }
            }
        }
    }
}

// ---------------------------------------------------------------------------
// fp16 flash attention on COMPACTED keys: 128-query tile, 256 threads,
// nkt = ceil(cnt/64) key tiles (data-dependent, ~16). K/V 4-slot ring
// (prefetch distance 2), 1 CTA barrier per key tile. Q fragments register-
// resident; P never touches smem; softmax in log2 domain (ex2).
// Tail masking is positional: compact key index >= cnt -> -1e9.
// smem: Q 128x36 + K 4x64x36 + V 4x64x36 = 92160 B -> 2 CTAs/SM.
// ---------------------------------------------------------------------------
#define AQ_OFF 0
#define AK_OFF (128*36)
#define AV_OFF (AK_OFF + 4*64*36)
#define ATTN_SMEM ((AV_OFF + 4*64*36)*4)

__global__ void __launch_bounds__(256, 2) attn_f16()
{
    extern __shared__ uint32_t sm[];

    const int qt  = blockIdx.x;
    const int h   = blockIdx.y;
    const int b   = blockIdx.z;
    const int tid = threadIdx.x;
    const int wid = tid >> 5;
    const int lane = tid & 31;
    const int gid = lane >> 2;
    const int tig = lane & 3;
    const int m0  = wid * 16;

    const __half* qb = g_q + ((size_t)(b*HH + h))*LL*DH + (size_t)qt*128*DH;
    const __half* kb = g_k + ((size_t)(b*HH + h))*LL*DH;
    const __half* vb = g_v + ((size_t)(b*HH + h))*DH*LL;
    const uint32_t smb = smem_u32(sm);

    const int cnt = g_cnt[b];
    const int nkt = (cnt + 63) >> 6;

    const int g  = lane >> 3;
    const int rr = lane & 7;
    const int a_row = (g & 1) * 8 + rr;
    const int a_kw  = (g >> 1) * 4;
    const int b_row = (g >> 1) * 8 + rr;
    const int b_kw  = (g & 1) * 4;

    #define A_ISSUE(kt_) do { \
        const int tb_ = (kt_) & 3; \
        const __half* ksrc_ = kb + (size_t)(kt_)*64*DH; \
        _Pragma("unroll") \
        for (int rep_ = 0; rep_ < 2; rep_++) { \
            int idx_ = rep_*256 + tid; \
            int r_ = idx_ >> 3, w_ = (idx_ & 7); \
            cp16(smb + (uint32_t)(AK_OFF + tb_*64*36 + r_*36 + w_*4)*4, \
                 ksrc_ + (size_t)r_*DH + w_*8); \
            cp16(smb + (uint32_t)(AV_OFF + tb_*64*36 + r_*36 + w_*4)*4, \
                 vb + (size_t)r_*LL + (kt_)*64 + w_*8); \
        } \
    } while (0)

    // prologue: Q + tile 0 in group 0; tile 1 in group 1
    #pragma unroll
    for (int rep = 0; rep < 4; rep++) {
        int idx = rep*256 + tid;
        int r = idx >> 3, w = idx & 7;
        cp16(smb + (uint32_t)(AQ_OFF + r*36 + w*4)*4, qb + (size_t)r*DH + w*8);
    }
    A_ISSUE(0);
    CP_COMMIT();
    A_ISSUE(1);
    CP_COMMIT();

    float accO[8][4];
    #pragma unroll
    for (int nt = 0; nt < 8; nt++)
        #pragma unroll
        for (int r = 0; r < 4; r++) accO[nt][r] = 0.f;
    float mi[2] = {-INFINITY, -INFINITY};
    float li[2] = {0.f, 0.f};

    uint32_t qf[4][4];   // register-resident Q fragments

    for (int kt = 0; kt < nkt; kt++) {
        const int tb = kt & 3;

        if (kt + 2 < nkt) A_ISSUE(kt + 2);
        CP_COMMIT();
        CP_WAIT2();
        __syncthreads();

        if (kt == 0) {
            const uint32_t Qb = smb + (uint32_t)(AQ_OFF + (m0 + a_row)*36)*4;
            #pragma unroll
            for (int ks = 0; ks < 4; ks++)
                ldsm_x4(qf[ks], Qb + (uint32_t)(ks*8 + a_kw)*4);
        }

        // S = Q K^T  (Q pre-scaled by 0.125*log2e)
        float s[8][4];
        #pragma unroll
        for (int nt = 0; nt < 8; nt++)
            #pragma unroll
            for (int r = 0; r < 4; r++) s[nt][r] = 0.f;

        const uint32_t Kb = smb + (uint32_t)(AK_OFF + tb*64*36)*4;
        #pragma unroll
        for (int ks = 0; ks < 4; ks++) {
            const int kb8 = ks * 8;
            #pragma unroll
            for (int j = 0; j < 4; j++) {
                uint32_t bf[4];
                ldsm_x4(bf, Kb + (uint32_t)((j*16 + b_row)*36 + kb8 + b_kw)*4);
                mma_f16(s[2*j],   qf[ks], bf[0], bf[1]);
                mma_f16(s[2*j+1], qf[ks], bf[2], bf[3]);
            }
        }

        // positional tail mask: compact key index >= cnt
        #pragma unroll
        for (int nt = 0; nt < 8; nt++) {
            const int c0 = kt*64 + nt*8 + tig*2;
            if (c0     >= cnt) { s[nt][0] = -1e9f; s[nt][2] = -1e9f; }
            if (c0 + 1 >= cnt) { s[nt][1] = -1e9f; s[nt][3] = -1e9f; }
        }

        // online softmax in log2 domain (rows gid, gid+8)
        #pragma unroll
        for (int half_ = 0; half_ < 2; half_++) {
            float rm = -INFINITY;
            #pragma unroll
            for (int nt = 0; nt < 8; nt++)
                rm = fmaxf(rm, fmaxf(s[nt][half_*2], s[nt][half_*2+1]));
            rm = fmaxf(rm, __shfl_xor_sync(0xffffffffu, rm, 1));
            rm = fmaxf(rm, __shfl_xor_sync(0xffffffffu, rm, 2));
            const float newm = fmaxf(mi[half_], rm);
            const float corr = ex2(mi[half_] - newm);
            float rs = 0.f;
            #pragma unroll
            for (int nt = 0; nt < 8; nt++) {
                s[nt][half_*2]   = ex2(s[nt][half_*2]   - newm);
                s[nt][half_*2+1] = ex2(s[nt][half_*2+1] - newm);
                rs += s[nt][half_*2] + s[nt][half_*2+1];
            }
            rs += __shfl_xor_sync(0xffffffffu, rs, 1);
            rs += __shfl_xor_sync(0xffffffffu, rs, 2);
            li[half_] = li[half_] * corr + rs;
            mi[half_] = newm;
            #pragma unroll
            for (int nt = 0; nt < 8; nt++) {
                accO[nt][half_*2]   *= corr;
                accO[nt][half_*2+1] *= corr;
            }
        }

        // O += P @ V — P built directly from S fragments
        const uint32_t Vb = smb + (uint32_t)(AV_OFF + tb*64*36)*4;
        #pragma unroll
        for (int ks = 0; ks < 4; ks++) {
            const int kb8 = ks * 8;
            uint32_t af[4];
            af[0] = pack2(s[2*ks  ][0], s[2*ks  ][1]);
            af[1] = pack2(s[2*ks  ][2], s[2*ks  ][3]);
            af[2] = pack2(s[2*ks+1][0], s[2*ks+1][1]);
            af[3] = pack2(s[2*ks+1][2], s[2*ks+1][3]);
            #pragma unroll
            for (int j = 0; j < 4; j++) {
                uint32_t bf[4];
                ldsm_x4(bf, Vb + (uint32_t)((j*16 + b_row)*36 + kb8 + b_kw)*4);
                mma_f16(accO[2*j],   af, bf[0], bf[1]);
                mma_f16(accO[2*j+1], af, bf[2], bf[3]);
            }
        }
    }
    #undef A_ISSUE

    const float inv0 = 1.f / li[0];
    const float inv1 = 1.f / li[1];
    const int r0 = qt*128 + m0 + gid;
    const int r1 = r0 + 8;
    #pragma unroll
    for (int nt = 0; nt < 8; nt++) {
        const int c = h*DH + nt*8 + tig*2;
        *(uint32_t*)&g_ctx[((size_t)(b*LL + r0))*DD + c] =
            pack2(accO[nt][0]*inv0, accO[nt][1]*inv0);
        *(uint32_t*)&g_ctx[((size_t)(b*LL + r1))*DD + c] =
            pack2(accO[nt][2]*inv1, accO[nt][3]*inv1);
    }
}

// ---------------------------------------------------------------------------
extern "C" void kernel_launch(void* const* d_in, const int* in_sizes, int n_in,
                              void* d_out, int out_size)
{
    const float* x  = (const float*)d_in[0];
    const int* mask = (const int*)d_in[1];
    const float* wq = (const float*)d_in[2];
    const float* bq = (const float*)d_in[3];
    const float* wk = (const float*)d_in[4];
    const float* bk = (const float*)d_in[5];
    const float* wv = (const float*)d_in[6];
    const float* bv = (const float*)d_in[7];
    const float* wo = (const float*)d_in[8];
    const float* bo = (const float*)d_in[9];
    float* out = (float*)d_out;

    cudaFuncSetAttribute(gemm_f16, cudaFuncAttributeMaxDynamicSharedMemorySize,
                         GEMM_SMEM);
    cudaFuncSetAttribute(attn_f16, cudaFuncAttributeMaxDynamicSharedMemorySize,
                         ATTN_SMEM);

    scan_kernel<<<BB, 256>>>(mask);

    const int ncvt = (int)(((size_t)MM*DD/4 + (size_t)DD*DD + 255) / 256);
    cvt_kernel<<<ncvt, 256>>>(x, wq, wk, wv, wo);

    // merged QKV: N = 3072
    dim3 gqkv(3*DD/128, MM/128);   // 24 x 64 blocks
    gemm_f16<<<gqkv, 256, GEMM_SMEM>>>(bq, bk, bv, nullptr, 0);

    dim3 ga(LL/128, HH, BB);       // 16 x 16 x 4 blocks
    attn_f16<<<ga, 256, ATTN_SMEM>>>();

    dim3 go(DD/128, MM/128);       // 8 x 64 blocks
    gemm_f16<<<go, 256, GEMM_SMEM>>>(bo, nullptr, nullptr, out, 3);
}

// round 16
// speedup vs baseline: 1.7561x; 1.1449x over previous
#include <cuda_runtime.h>
#include <cuda_fp16.h>
#include <math.h>
#include <stdint.h>

#define BB   4
#define HH   16
#define LL   2048
#define DD   1024
#define DH   64
#define MM   (BB*LL)   // 8192 tokens

// Scratch (device globals: allocation-free, graph-capturable). All fp16.
__device__ __half g_q[(size_t)BB*HH*LL*DH];    // (B,H,L,dh), pre-scaled by 0.125*log2e
__device__ __half g_k[(size_t)BB*HH*LL*DH];    // (B,H,Lc,dh) COMPACTED keys
__device__ __half g_v[(size_t)BB*HH*DH*LL];    // (B,H,dh,Lc) TRANSPOSED + COMPACTED
__device__ __half g_ctx[(size_t)MM*DD];        // (B,L,D)
__device__ __half g_xt[(size_t)MM*DD];         // x in fp16
__device__ __half g_xc[(size_t)BB*LL*DD];      // x rows compacted per batch
__device__ __half g_wt[(size_t)4*DD*DD];       // wq,wk,wv,wo in fp16 (contiguous!)
__device__ int    g_cpos[(size_t)BB*LL];       // compact position or -1 if masked
__device__ int    g_cnt[BB];                   // unmasked count per batch

// ---------------- helpers ----------------
__device__ __forceinline__ void mma_f16(float c[4], const uint32_t a[4],
                                        uint32_t b0, uint32_t b1) {
    asm volatile(
        "mma.sync.aligned.m16n8k16.row.col.f32.f16.f16.f32 "
        "{%0,%1,%2,%3}, {%4,%5,%6,%7}, {%8,%9}, {%0,%1,%2,%3};"
        : "+f"(c[0]), "+f"(c[1]), "+f"(c[2]), "+f"(c[3])
        : "r"(a[0]), "r"(a[1]), "r"(a[2]), "r"(a[3]), "r"(b0), "r"(b1));
}
__device__ __forceinline__ void ldsm_x4(uint32_t r[4], uint32_t saddr) {
    asm volatile("ldmatrix.sync.aligned.m8n8.x4.shared.b16 {%0,%1,%2,%3}, [%4];"
                 : "=r"(r[0]), "=r"(r[1]), "=r"(r[2]), "=r"(r[3]) : "r"(saddr));
}
__device__ __forceinline__ void cp16(uint32_t saddr, const void* gptr) {
    asm volatile("cp.async.cg.shared.global [%0], [%1], 16;"
                 :: "r"(saddr), "l"(gptr));
}
#define CP_COMMIT() asm volatile("cp.async.commit_group;")
#define CP_WAIT1()  asm volatile("cp.async.wait_group 1;")
#define CP_WAIT2()  asm volatile("cp.async.wait_group 2;")

__device__ __forceinline__ uint32_t pack2(float a, float b) {
    __half2 h = __floats2half2_rn(a, b);
    return *reinterpret_cast<uint32_t*>(&h);
}
__device__ __forceinline__ float ex2(float x) {
    float r;
    asm("ex2.approx.f32 %0, %1;" : "=f"(r) : "f"(x));
    return r;
}
__device__ __forceinline__ uint32_t smem_u32(const void* p) {
    uint32_t a;
    asm("{ .reg .u64 t; cvta.to.shared.u64 t, %1; cvt.u32.u64 %0, t; }"
        : "=r"(a) : "l"(p));
    return a;
}

// ---------------------------------------------------------------------------
// Per-batch exclusive prefix scan of unmasked positions.
// ---------------------------------------------------------------------------
__global__ void __launch_bounds__(256) scan_kernel(const int* __restrict__ mask)
{
    __shared__ int warp_sums[8];
    const int b   = blockIdx.x;
    const int tid = threadIdx.x;
    const int* m  = mask + (size_t)b * LL;
    const int base = tid * 8;

    int v[8], s = 0;
    #pragma unroll
    for (int i = 0; i < 8; i++) { v[i] = (m[base + i] == 0); s += v[i]; }

    const int lane = tid & 31, wid = tid >> 5;
    int ps = s;
    #pragma unroll
    for (int off = 1; off < 32; off <<= 1) {
        int t = __shfl_up_sync(0xffffffffu, ps, off);
        if (lane >= off) ps += t;
    }
    if (lane == 31) warp_sums[wid] = ps;
    __syncthreads();
    if (tid == 0) {
        int acc = 0;
        #pragma unroll
        for (int w = 0; w < 8; w++) { int t = warp_sums[w]; warp_sums[w] = acc; acc += t; }
        g_cnt[b] = acc;
    }
    __syncthreads();

    int excl = warp_sums[wid] + ps - s;
    #pragma unroll
    for (int i = 0; i < 8; i++) {
        g_cpos[(size_t)b * LL + base + i] = v[i] ? excl : -1;
        excl += v[i];
    }
}

// ---------------------------------------------------------------------------
// Convert x and the 4 weights to fp16.
// ---------------------------------------------------------------------------
__global__ void __launch_bounds__(256) cvt_kernel(
    const float* __restrict__ x,
    const float* __restrict__ wq, const float* __restrict__ wk,
    const float* __restrict__ wv, const float* __restrict__ wo)
{
    const size_t NX = (size_t)MM * DD / 4;
    const size_t NW = (size_t)DD * DD / 4;
    size_t i = (size_t)blockIdx.x * blockDim.x + threadIdx.x;
    if (i >= NX + 4 * NW) return;
    const float* src;
    __half* dst;
    size_t off;
    if (i < NX) { src = x; dst = g_xt; off = i; }
    else {
        size_t j = i - NX;
        int w = (int)(j / NW);
        off = j % NW;
        src = (w == 0) ? wq : (w == 1) ? wk : (w == 2) ? wv : wo;
        dst = g_wt + (size_t)w * DD * DD;
    }
    float4 v = ((const float4*)src)[off];
    ((__half2*)dst)[off*2]   = __floats2half2_rn(v.x, v.y);
    ((__half2*)dst)[off*2+1] = __floats2half2_rn(v.z, v.w);
}

// ---------------------------------------------------------------------------
// Gather unmasked x rows (fp16) into per-batch compacted buffer.
// One block per token row, 128 threads x 16B = 2048B row copy.
// ---------------------------------------------------------------------------
__global__ void __launch_bounds__(128) gather_kernel()
{
    const int row = blockIdx.x;              // global token row
    const int b   = row >> 11;
    const int cp  = g_cpos[row];
    if (cp < 0) return;
    const uint4* src = (const uint4*)(g_xt + (size_t)row * DD);
    uint4* dst = (uint4*)(g_xc + ((size_t)b * LL + cp) * DD);
    dst[threadIdx.x] = src[threadIdx.x];
}

// ---------------------------------------------------------------------------
// fp16 GEMM (R12 mainloop): 128x128 tile, 256 threads, BK=32, 4-stage
// cp.async ring, ldmatrix.x4, register double-buffered fragments.
// mode 0: Q projection (N=1024), out g_q scaled 0.125*log2e
// mode 1: KV merged (N=2048, wk||wv), A = compacted x per batch.
//         blockIdx.y encodes (batch<<4 | mtile); early-exit past cnt[b].
//         K stored compact; V stored transposed+compact.
// mode 3: O projection (fp32 out).
// ---------------------------------------------------------------------------
#define GROW 20
#define GSTW (2*128*GROW)
#define GSTAGES 4
#define GEMM_SMEM (GSTAGES*GSTW*4)  // 81920 B -> 2 CTAs/SM

__global__ void __launch_bounds__(256, 2) gemm_f16(
    const float* __restrict__ bias0, const float* __restrict__ bias1,
    float* __restrict__ Oext, int mode)
{
    int bm, batch = 0;
    const __half* A;
    const __half* W;
    if (mode == 1) {
        batch = blockIdx.y >> 4;
        const int mtile = blockIdx.y & 15;
        bm = mtile * 128;
        if (bm >= g_cnt[batch]) return;     // block-uniform early exit
        A = g_xc + (size_t)batch * LL * DD;
        W = g_wt + (size_t)DD * DD;         // wk || wv
    } else {
        bm = blockIdx.y * 128;
        A = (mode == 3) ? g_ctx : g_xt;
        W = (mode == 3) ? (g_wt + (size_t)3*DD*DD) : g_wt;
    }

    extern __shared__ uint32_t sm[];

    const int tid  = threadIdx.x;
    const int wid  = tid >> 5;
    const int lane = tid & 31;
    const int gid  = lane >> 2;
    const int tig  = lane & 3;
    const int warp_m = (wid & 1) * 64;
    const int warp_n = (wid >> 1) * 32;
    const int bn = blockIdx.x * 128;

    const int lmat = tid >> 7;
    const int lrow = tid & 127;
    const __half* grow = lmat ? (W + (size_t)(bn + lrow) * DD)
                              : (A + (size_t)(bm + lrow) * DD);
    const uint32_t smb = smem_u32(sm);
    const uint32_t ldst = smb + (uint32_t)(lmat*128 + lrow) * GROW * 4;

    const int g  = lane >> 3;
    const int rr = lane & 7;
    const int a_row = warp_m + (g & 1) * 8 + rr;
    const int a_kw  = (g >> 1) * 4;
    const int b_row = 128 + warp_n + (g >> 1) * 8 + rr;
    const int b_kw  = (g & 1) * 4;
    const uint32_t a_off0 = (uint32_t)((a_row +  0)*GROW + a_kw)*4;
    const uint32_t a_off1 = (uint32_t)((a_row + 16)*GROW + a_kw)*4;
    const uint32_t a_off2 = (uint32_t)((a_row + 32)*GROW + a_kw)*4;
    const uint32_t a_off3 = (uint32_t)((a_row + 48)*GROW + a_kw)*4;
    const uint32_t b_off0 = (uint32_t)((b_row +  0)*GROW + b_kw)*4;
    const uint32_t b_off1 = (uint32_t)((b_row + 16)*GROW + b_kw)*4;

    float acc[4][4][4];
    #pragma unroll
    for (int mt = 0; mt < 4; mt++)
        #pragma unroll
        for (int nt = 0; nt < 4; nt++)
            #pragma unroll
            for (int r = 0; r < 4; r++) acc[mt][nt][r] = 0.f;

    uint32_t afr[2][4][4];
    uint32_t bfr[2][2][4];

    #define LOAD_FRAGS(set_, Ab_, ks_) do { \
        ldsm_x4(afr[set_][0], (Ab_) + a_off0 + (ks_)*32); \
        ldsm_x4(afr[set_][1], (Ab_) + a_off1 + (ks_)*32); \
        ldsm_x4(afr[set_][2], (Ab_) + a_off2 + (ks_)*32); \
        ldsm_x4(afr[set_][3], (Ab_) + a_off3 + (ks_)*32); \
        ldsm_x4(bfr[set_][0], (Ab_) + b_off0 + (ks_)*32); \
        ldsm_x4(bfr[set_][1], (Ab_) + b_off1 + (ks_)*32); \
    } while (0)

    #define MMA_SET(set_) do { \
        _Pragma("unroll") \
        for (int j_ = 0; j_ < 2; j_++) \
            _Pragma("unroll") \
            for (int mt_ = 0; mt_ < 4; mt_++) { \
                mma_f16(acc[mt_][2*j_],   afr[set_][mt_], bfr[set_][j_][0], bfr[set_][j_][1]); \
                mma_f16(acc[mt_][2*j_+1], afr[set_][mt_], bfr[set_][j_][2], bfr[set_][j_][3]); \
            } \
    } while (0)

    #define G_ISSUE(t_) do { \
        uint32_t d_ = ldst + (uint32_t)((t_) & 3) * (GSTW*4); \
        const __half* s_ = grow + (t_) * 32; \
        cp16(d_,      s_);      cp16(d_ + 16, s_ + 8); \
        cp16(d_ + 32, s_ + 16); cp16(d_ + 48, s_ + 24); \
    } while (0)

    G_ISSUE(0); CP_COMMIT();
    G_ISSUE(1); CP_COMMIT();
    CP_WAIT1();
    __syncthreads();
    LOAD_FRAGS(0, smb, 0);

    for (int i = 0; i < 32; i++) {
        const uint32_t Abi = smb + (uint32_t)(i & 3) * (GSTW*4);
        LOAD_FRAGS(1, Abi, 1);
        if (i + 2 < 32) G_ISSUE(i + 2);
        CP_COMMIT();
        MMA_SET(0);
        if (i + 1 < 32) {
            CP_WAIT1();
            __syncthreads();
            const uint32_t Abn = smb + (uint32_t)((i+1) & 3) * (GSTW*4);
            LOAD_FRAGS(0, Abn, 0);
        }
        MMA_SET(1);
    }
    #undef G_ISSUE
    #undef LOAD_FRAGS
    #undef MMA_SET

    // epilogue
    // mode 1: which = bn>>10 (0=K, 1=V); else Q (mode 0) / O (mode 3)
    const int which = (mode == 1) ? (bn >> 10) : mode;
    const float* bias = (mode == 1 && which == 1) ? bias1 : bias0;
    const float sc = (mode == 0) ? 0.125f * 1.4426950408889634f : 1.f;

    #pragma unroll
    for (int mt = 0; mt < 4; mt++) {
        #pragma unroll
        for (int nt = 0; nt < 4; nt++) {
            const int col = bn + warp_n + nt*8 + tig*2;
            const int lc  = col & 1023;
            const float b0 = bias[lc];
            const float b1 = bias[lc + 1];
            #pragma unroll
            for (int half_ = 0; half_ < 2; half_++) {
                const int m = bm + warp_m + mt*16 + gid + half_*8;
                float vx = (acc[mt][nt][half_*2 + 0] + b0) * sc;
                float vy = (acc[mt][nt][half_*2 + 1] + b1) * sc;
                if (mode == 3) {
                    *(float2*)&Oext[(size_t)m * DD + lc] = make_float2(vx, vy);
                } else if (mode == 0) {
                    const int bb = m >> 11;
                    const int ll = m & (LL - 1);
                    const int h  = lc >> 6;
                    const int c  = lc & (DH - 1);
                    *(uint32_t*)&g_q[(((size_t)(bb*HH + h)*LL) + ll)*DH + c] =
                        pack2(vx, vy);
                } else {   // mode 1: m is already the compact row within batch
                    const int h  = lc >> 6;
                    const int c  = lc & (DH - 1);
                    if (which == 1) {   // V transposed+compacted (B,H,dh,Lc)
                        const size_t base = ((size_t)(batch*HH + h)) * DH * LL;
                        g_v[base + (size_t)c    *LL + m] = __float2half_rn(vx);
                        g_v[base + (size_t)(c+1)*LL + m] = __float2half_rn(vy);
                    } else {            // K compacted
                        *(uint32_t*)&g_k[(((size_t)(batch*HH + h)*LL) + m)*DH + c] =
                            pack2(vx, vy);
                    }
                }
            }
        }
    }
}

// ---------------------------------------------------------------------------
// fp16 flash attention on COMPACTED keys (R15-best, unchanged).
// ---------------------------------------------------------------------------
#define AQ_OFF 0
#define AK_OFF (128*36)
#define AV_OFF (AK_OFF + 4*64*36)
#define ATTN_SMEM ((AV_OFF + 4*64*36)*4)

__global__ void __launch_bounds__(256, 2) attn_f16()
{
    extern __shared__ uint32_t sm[];

    const int qt  = blockIdx.x;
    const int h   = blockIdx.y;
    const int b   = blockIdx.z;
    const int tid = threadIdx.x;
    const int wid = tid >> 5;
    const int lane = tid & 31;
    const int gid = lane >> 2;
    const int tig = lane & 3;
    const int m0  = wid * 16;

    const __half* qb = g_q + ((size_t)(b*HH + h))*LL*DH + (size_t)qt*128*DH;
    const __half* kb = g_k + ((size_t)(b*HH + h))*LL*DH;
    const __half* vb = g_v + ((size_t)(b*HH + h))*DH*LL;
    const uint32_t smb = smem_u32(sm);

    const int cnt = g_cnt[b];
    const int nkt = (cnt + 63) >> 6;

    const int g  = lane >> 3;
    const int rr = lane & 7;
    const int a_row = (g & 1) * 8 + rr;
    const int a_kw  = (g >> 1) * 4;
    const int b_row = (g >> 1) * 8 + rr;
    const int b_kw  = (g & 1) * 4;

    #define A_ISSUE(kt_) do { \
        const int tb_ = (kt_) & 3; \
        const __half* ksrc_ = kb + (size_t)(kt_)*64*DH; \
        _Pragma("unroll") \
        for (int rep_ = 0; rep_ < 2; rep_++) { \
            int idx_ = rep_*256 + tid; \
            int r_ = idx_ >> 3, w_ = (idx_ & 7); \
            cp16(smb + (uint32_t)(AK_OFF + tb_*64*36 + r_*36 + w_*4)*4, \
                 ksrc_ + (size_t)r_*DH + w_*8); \
            cp16(smb + (uint32_t)(AV_OFF + tb_*64*36 + r_*36 + w_*4)*4, \
                 vb + (size_t)r_*LL + (kt_)*64 + w_*8); \
        } \
    } while (0)

    #pragma unroll
    for (int rep = 0; rep < 4; rep++) {
        int idx = rep*256 + tid;
        int r = idx >> 3, w = idx & 7;
        cp16(smb + (uint32_t)(AQ_OFF + r*36 + w*4)*4, qb + (size_t)r*DH + w*8);
    }
    A_ISSUE(0);
    CP_COMMIT();
    A_ISSUE(1);
    CP_COMMIT();

    float accO[8][4];
    #pragma unroll
    for (int nt = 0; nt < 8; nt++)
        #pragma unroll
        for (int r = 0; r < 4; r++) accO[nt][r] = 0.f;
    float mi[2] = {-INFINITY, -INFINITY};
    float li[2] = {0.f, 0.f};

    uint32_t qf[4][4];

    for (int kt = 0; kt < nkt; kt++) {
        const int tb = kt & 3;

        if (kt + 2 < nkt) A_ISSUE(kt + 2);
        CP_COMMIT();
        CP_WAIT2();
        __syncthreads();

        if (kt == 0) {
            const uint32_t Qb = smb + (uint32_t)(AQ_OFF + (m0 + a_row)*36)*4;
            #pragma unroll
            for (int ks = 0; ks < 4; ks++)
                ldsm_x4(qf[ks], Qb + (uint32_t)(ks*8 + a_kw)*4);
        }

        float s[8][4];
        #pragma unroll
        for (int nt = 0; nt < 8; nt++)
            #pragma unroll
            for (int r = 0; r < 4; r++) s[nt][r] = 0.f;

        const uint32_t Kb = smb + (uint32_t)(AK_OFF + tb*64*36)*4;
        #pragma unroll
        for (int ks = 0; ks < 4; ks++) {
            const int kb8 = ks * 8;
            #pragma unroll
            for (int j = 0; j < 4; j++) {
                uint32_t bf[4];
                ldsm_x4(bf, Kb + (uint32_t)((j*16 + b_row)*36 + kb8 + b_kw)*4);
                mma_f16(s[2*j],   qf[ks], bf[0], bf[1]);
                mma_f16(s[2*j+1], qf[ks], bf[2], bf[3]);
            }
        }

        // positional tail mask
        #pragma unroll
        for (int nt = 0; nt < 8; nt++) {
            const int c0 = kt*64 + nt*8 + tig*2;
            if (c0     >= cnt) { s[nt][0] = -1e9f; s[nt][2] = -1e9f; }
            if (c0 + 1 >= cnt) { s[nt][1] = -1e9f; s[nt][3] = -1e9f; }
        }

        // online softmax in log2 domain
        #pragma unroll
        for (int half_ = 0; half_ < 2; half_++) {
            float rm = -INFINITY;
            #pragma unroll
            for (int nt = 0; nt < 8; nt++)
                rm = fmaxf(rm, fmaxf(s[nt][half_*2], s[nt][half_*2+1]));
            rm = fmaxf(rm, __shfl_xor_sync(0xffffffffu, rm, 1));
            rm = fmaxf(rm, __shfl_xor_sync(0xffffffffu, rm, 2));
            const float newm = fmaxf(mi[half_], rm);
            const float corr = ex2(mi[half_] - newm);
            float rs = 0.f;
            #pragma unroll
            for (int nt = 0; nt < 8; nt++) {
                s[nt][half_*2]   = ex2(s[nt][half_*2]   - newm);
                s[nt][half_*2+1] = ex2(s[nt][half_*2+1] - newm);
                rs += s[nt][half_*2] + s[nt][half_*2+1];
            }
            rs += __shfl_xor_sync(0xffffffffu, rs, 1);
            rs += __shfl_xor_sync(0xffffffffu, rs, 2);
            li[half_] = li[half_] * corr + rs;
            mi[half_] = newm;
            #pragma unroll
            for (int nt = 0; nt < 8; nt++) {
                accO[nt][half_*2]   *= corr;
                accO[nt][half_*2+1] *= corr;
            }
        }

        // O += P @ V
        const uint32_t Vb = smb + (uint32_t)(AV_OFF + tb*64*36)*4;
        #pragma unroll
        for (int ks = 0; ks < 4; ks++) {
            const int kb8 = ks * 8;
            uint32_t af[4];
            af[0] = pack2(s[2*ks  ][0], s[2*ks  ][1]);
            af[1] = pack2(s[2*ks  ][2], s[2*ks  ][3]);
            af[2] = pack2(s[2*ks+1][0], s[2*ks+1][1]);
            af[3] = pack2(s[2*ks+1][2], s[2*ks+1][3]);
            #pragma unroll
            for (int j = 0; j < 4; j++) {
                uint32_t bf[4];
                ldsm_x4(bf, Vb + (uint32_t)((j*16 + b_row)*36 + kb8 + b_kw)*4);
                mma_f16(accO[2*j],   af, bf[0], bf[1]);
                mma_f16(accO[2*j+1], af, bf[2], bf[3]);
            }
        }
    }
    #undef A_ISSUE

    const float inv0 = 1.f / li[0];
    const float inv1 = 1.f / li[1];
    const int r0 = qt*128 + m0 + gid;
    const int r1 = r0 + 8;
    #pragma unroll
    for (int nt = 0; nt < 8; nt++) {
        const int c = h*DH + nt*8 + tig*2;
        *(uint32_t*)&g_ctx[((size_t)(b*LL + r0))*DD + c] =
            pack2(accO[nt][0]*inv0, accO[nt][1]*inv0);
        *(uint32_t*)&g_ctx[((size_t)(b*LL + r1))*DD + c] =
            pack2(accO[nt][2]*inv1, accO[nt][3]*inv1);
    }
}

// ---------------------------------------------------------------------------
extern "C" void kernel_launch(void* const* d_in, const int* in_sizes, int n_in,
                              void* d_out, int out_size)
{
    const float* x  = (const float*)d_in[0];
    const int* mask = (const int*)d_in[1];
    const float* wq = (const float*)d_in[2];
    const float* bq = (const float*)d_in[3];
    const float* wk = (const float*)d_in[4];
    const float* bk = (const float*)d_in[5];
    const float* wv = (const float*)d_in[6];
    const float* bv = (const float*)d_in[7];
    const float* wo = (const float*)d_in[8];
    const float* bo = (const float*)d_in[9];
    float* out = (float*)d_out;

    cudaFuncSetAttribute(gemm_f16, cudaFuncAttributeMaxDynamicSharedMemorySize,
                         GEMM_SMEM);
    cudaFuncSetAttribute(attn_f16, cudaFuncAttributeMaxDynamicSharedMemorySize,
                         ATTN_SMEM);

    scan_kernel<<<BB, 256>>>(mask);

    const int ncvt = (int)(((size_t)MM*DD/4 + (size_t)DD*DD + 255) / 256);
    cvt_kernel<<<ncvt, 256>>>(x, wq, wk, wv, wo);

    gather_kernel<<<MM, 128>>>();

    // Q projection: N = 1024, all rows
    dim3 gq(DD/128, MM/128);       // 8 x 64
    gemm_f16<<<gq, 256, GEMM_SMEM>>>(bq, nullptr, nullptr, 0);

    // KV merged projection on compacted rows: N = 2048, up to 16 tiles/batch
    dim3 gkv(2*DD/128, BB*16);     // 16 x 64 (blocks past cnt exit early)
    gemm_f16<<<gkv, 256, GEMM_SMEM>>>(bk, bv, nullptr, 1);

    dim3 ga(LL/128, HH, BB);       // 16 x 16 x 4
    attn_f16<<<ga, 256, ATTN_SMEM>>>();

    dim3 go(DD/128, MM/128);       // 8 x 64
    gemm_f16<<<go, 256, GEMM_SMEM>>>(bo, nullptr, out, 3);
}

// round 17
// speedup vs baseline: 1.8871x; 1.0746x over previous
#include <cuda_runtime.h>
#include <cuda_fp16.h>
#include <math.h>
#include <stdint.h>

#define BB   4
#define HH   16
#define LL   2048
#define DD   1024
#define DH   64
#define MM   (BB*LL)   // 8192 tokens

// Scratch (device globals: allocation-free, graph-capturable). All fp16.
__device__ __half g_q[(size_t)BB*HH*LL*DH];    // (B,H,L,dh), pre-scaled by 0.125*log2e
__device__ __half g_k[(size_t)BB*HH*LL*DH];    // (B,H,Lc,dh) COMPACTED keys
__device__ __half g_v[(size_t)BB*HH*DH*LL];    // (B,H,dh,Lc) TRANSPOSED + COMPACTED
__device__ __half g_ctx[(size_t)MM*DD];        // (B,L,D)
__device__ __half g_xt[(size_t)MM*DD];         // x in fp16
__device__ __half g_xc[(size_t)BB*LL*DD];      // x rows compacted per batch
__device__ __half g_wt[(size_t)4*DD*DD];       // wq,wk,wv,wo in fp16 (contiguous!)
__device__ int    g_cpos[(size_t)BB*LL];       // compact position or -1 if masked
__device__ int    g_cnt[BB];                   // unmasked count per batch

// ---------------- helpers ----------------
__device__ __forceinline__ void mma_f16(float c[4], const uint32_t a[4],
                                        uint32_t b0, uint32_t b1) {
    asm volatile(
        "mma.sync.aligned.m16n8k16.row.col.f32.f16.f16.f32 "
        "{%0,%1,%2,%3}, {%4,%5,%6,%7}, {%8,%9}, {%0,%1,%2,%3};"
        : "+f"(c[0]), "+f"(c[1]), "+f"(c[2]), "+f"(c[3])
        : "r"(a[0]), "r"(a[1]), "r"(a[2]), "r"(a[3]), "r"(b0), "r"(b1));
}
__device__ __forceinline__ void ldsm_x4(uint32_t r[4], uint32_t saddr) {
    asm volatile("ldmatrix.sync.aligned.m8n8.x4.shared.b16 {%0,%1,%2,%3}, [%4];"
                 : "=r"(r[0]), "=r"(r[1]), "=r"(r[2]), "=r"(r[3]) : "r"(saddr));
}
__device__ __forceinline__ void cp16(uint32_t saddr, const void* gptr) {
    asm volatile("cp.async.cg.shared.global [%0], [%1], 16;"
                 :: "r"(saddr), "l"(gptr));
}
#define CP_COMMIT() asm volatile("cp.async.commit_group;")
#define CP_WAIT1()  asm volatile("cp.async.wait_group 1;")
#define CP_WAIT2()  asm volatile("cp.async.wait_group 2;")

__device__ __forceinline__ uint32_t pack2(float a, float b) {
    __half2 h = __floats2half2_rn(a, b);
    return *reinterpret_cast<uint32_t*>(&h);
}
__device__ __forceinline__ float ex2(float x) {
    float r;
    asm("ex2.approx.f32 %0, %1;" : "=f"(r) : "f"(x));
    return r;
}
__device__ __forceinline__ uint32_t smem_u32(const void* p) {
    uint32_t a;
    asm("{ .reg .u64 t; cvta.to.shared.u64 t, %1; cvt.u32.u64 %0, t; }"
        : "=r"(a) : "l"(p));
    return a;
}

// ---------------------------------------------------------------------------
// Per-batch exclusive prefix scan of unmasked positions.
// ---------------------------------------------------------------------------
__global__ void __launch_bounds__(256) scan_kernel(const int* __restrict__ mask)
{
    __shared__ int warp_sums[8];
    const int b   = blockIdx.x;
    const int tid = threadIdx.x;
    const int* m  = mask + (size_t)b * LL;
    const int base = tid * 8;

    int v[8], s = 0;
    #pragma unroll
    for (int i = 0; i < 8; i++) { v[i] = (m[base + i] == 0); s += v[i]; }

    const int lane = tid & 31, wid = tid >> 5;
    int ps = s;
    #pragma unroll
    for (int off = 1; off < 32; off <<= 1) {
        int t = __shfl_up_sync(0xffffffffu, ps, off);
        if (lane >= off) ps += t;
    }
    if (lane == 31) warp_sums[wid] = ps;
    __syncthreads();
    if (tid == 0) {
        int acc = 0;
        #pragma unroll
        for (int w = 0; w < 8; w++) { int t = warp_sums[w]; warp_sums[w] = acc; acc += t; }
        g_cnt[b] = acc;
    }
    __syncthreads();

    int excl = warp_sums[wid] + ps - s;
    #pragma unroll
    for (int i = 0; i < 8; i++) {
        g_cpos[(size_t)b * LL + base + i] = v[i] ? excl : -1;
        excl += v[i];
    }
}

// ---------------------------------------------------------------------------
// Convert x and the 4 weights to fp16; ALSO scatter unmasked x rows into the
// per-batch compacted buffer g_xc (gather fused; requires scan done).
// ---------------------------------------------------------------------------
__global__ void __launch_bounds__(256) cvt_kernel(
    const float* __restrict__ x,
    const float* __restrict__ wq, const float* __restrict__ wk,
    const float* __restrict__ wv, const float* __restrict__ wo)
{
    const size_t NX = (size_t)MM * DD / 4;
    const size_t NW = (size_t)DD * DD / 4;
    size_t i = (size_t)blockIdx.x * blockDim.x + threadIdx.x;
    if (i >= NX + 4 * NW) return;
    if (i < NX) {
        float4 v = ((const float4*)x)[i];
        __half2 h0 = __floats2half2_rn(v.x, v.y);
        __half2 h1 = __floats2half2_rn(v.z, v.w);
        ((__half2*)g_xt)[i*2]   = h0;
        ((__half2*)g_xt)[i*2+1] = h1;
        const int row = (int)(i >> 8);            // DD/4 = 256 float4 per row
        const int c4  = (int)(i & 255);
        const int cp  = g_cpos[row];
        if (cp >= 0) {
            const int b = row >> 11;
            __half2* dst = (__half2*)(g_xc + ((size_t)b*LL + cp)*DD) + c4*2;
            dst[0] = h0;
            dst[1] = h1;
        }
    } else {
        size_t j = i - NX;
        int w = (int)(j / NW);
        size_t off = j % NW;
        const float* src = (w == 0) ? wq : (w == 1) ? wk : (w == 2) ? wv : wo;
        __half* dst = g_wt + (size_t)w * DD * DD;
        float4 v = ((const float4*)src)[off];
        ((__half2*)dst)[off*2]   = __floats2half2_rn(v.x, v.y);
        ((__half2*)dst)[off*2+1] = __floats2half2_rn(v.z, v.w);
    }
}

// ---------------------------------------------------------------------------
// fp16 GEMM (R12 mainloop): 128x128 tile, 256 threads, BK=32, 4-stage
// cp.async ring, ldmatrix.x4, register double-buffered fragments.
// mode 0: MERGED Q + KV projections in ONE launch (1D grid, 1536 blocks):
//   blocks [0,512):   Q tiles (all rows, N=1024), scaled 0.125*log2e
//   blocks [512,1536): KV tiles (compacted rows per batch, N=2048 wk||wv),
//                      early-exit past cnt[b]; K compact, V transposed+compact
// mode 3: O projection (2D grid, fp32 out).
// ---------------------------------------------------------------------------
#define GROW 20
#define GSTW (2*128*GROW)
#define GSTAGES 4
#define GEMM_SMEM (GSTAGES*GSTW*4)  // 81920 B -> 2 CTAs/SM

__global__ void __launch_bounds__(256, 2) gemm_f16(
    const float* __restrict__ bq_, const float* __restrict__ bk_,
    const float* __restrict__ bv_, float* __restrict__ Oext,
    int mode)
{
    int bm, bn, batch = 0, which;
    const __half* A;
    const __half* W;
    if (mode == 3) {
        bm = blockIdx.y * 128;
        bn = blockIdx.x * 128;
        A = g_ctx;
        W = g_wt + (size_t)3*DD*DD;
        which = 3;
    } else {
        int bid = blockIdx.x;
        if (bid < 512) {            // Q: 8 N-tiles x 64 M-tiles
            bn = (bid & 7) * 128;
            bm = (bid >> 3) * 128;
            A = g_xt;
            W = g_wt;
            which = 0;
        } else {                    // KV: 16 N-tiles x (4 batch x 16 mtile)
            bid -= 512;
            bn = (bid & 15) * 128;
            const int rest = bid >> 4;       // 0..63
            batch = rest >> 4;
            bm = (rest & 15) * 128;
            if (bm >= g_cnt[batch]) return;  // block-uniform early exit
            A = g_xc + (size_t)batch * LL * DD;
            W = g_wt + (size_t)DD * DD;      // wk || wv
            which = 1 + (bn >> 10);          // 1=K, 2=V
        }
    }

    extern __shared__ uint32_t sm[];

    const int tid  = threadIdx.x;
    const int wid  = tid >> 5;
    const int lane = tid & 31;
    const int gid  = lane >> 2;
    const int tig  = lane & 3;
    const int warp_m = (wid & 1) * 64;
    const int warp_n = (wid >> 1) * 32;

    const int lmat = tid >> 7;
    const int lrow = tid & 127;
    const __half* grow = lmat ? (W + (size_t)(bn + lrow) * DD)
                              : (A + (size_t)(bm + lrow) * DD);
    const uint32_t smb = smem_u32(sm);
    const uint32_t ldst = smb + (uint32_t)(lmat*128 + lrow) * GROW * 4;

    const int g  = lane >> 3;
    const int rr = lane & 7;
    const int a_row = warp_m + (g & 1) * 8 + rr;
    const int a_kw  = (g >> 1) * 4;
    const int b_row = 128 + warp_n + (g >> 1) * 8 + rr;
    const int b_kw  = (g & 1) * 4;
    const uint32_t a_off0 = (uint32_t)((a_row +  0)*GROW + a_kw)*4;
    const uint32_t a_off1 = (uint32_t)((a_row + 16)*GROW + a_kw)*4;
    const uint32_t a_off2 = (uint32_t)((a_row + 32)*GROW + a_kw)*4;
    const uint32_t a_off3 = (uint32_t)((a_row + 48)*GROW + a_kw)*4;
    const uint32_t b_off0 = (uint32_t)((b_row +  0)*GROW + b_kw)*4;
    const uint32_t b_off1 = (uint32_t)((b_row + 16)*GROW + b_kw)*4;

    float acc[4][4][4];
    #pragma unroll
    for (int mt = 0; mt < 4; mt++)
        #pragma unroll
        for (int nt = 0; nt < 4; nt++)
            #pragma unroll
            for (int r = 0; r < 4; r++) acc[mt][nt][r] = 0.f;

    uint32_t afr[2][4][4];
    uint32_t bfr[2][2][4];

    #define LOAD_FRAGS(set_, Ab_, ks_) do { \
        ldsm_x4(afr[set_][0], (Ab_) + a_off0 + (ks_)*32); \
        ldsm_x4(afr[set_][1], (Ab_) + a_off1 + (ks_)*32); \
        ldsm_x4(afr[set_][2], (Ab_) + a_off2 + (ks_)*32); \
        ldsm_x4(afr[set_][3], (Ab_) + a_off3 + (ks_)*32); \
        ldsm_x4(bfr[set_][0], (Ab_) + b_off0 + (ks_)*32); \
        ldsm_x4(bfr[set_][1], (Ab_) + b_off1 + (ks_)*32); \
    } while (0)

    #define MMA_SET(set_) do { \
        _Pragma("unroll") \
        for (int j_ = 0; j_ < 2; j_++) \
            _Pragma("unroll") \
            for (int mt_ = 0; mt_ < 4; mt_++) { \
                mma_f16(acc[mt_][2*j_],   afr[set_][mt_], bfr[set_][j_][0], bfr[set_][j_][1]); \
                mma_f16(acc[mt_][2*j_+1], afr[set_][mt_], bfr[set_][j_][2], bfr[set_][j_][3]); \
            } \
    } while (0)

    #define G_ISSUE(t_) do { \
        uint32_t d_ = ldst + (uint32_t)((t_) & 3) * (GSTW*4); \
        const __half* s_ = grow + (t_) * 32; \
        cp16(d_,      s_);      cp16(d_ + 16, s_ + 8); \
        cp16(d_ + 32, s_ + 16); cp16(d_ + 48, s_ + 24); \
    } while (0)

    G_ISSUE(0); CP_COMMIT();
    G_ISSUE(1); CP_COMMIT();
    CP_WAIT1();
    __syncthreads();
    LOAD_FRAGS(0, smb, 0);

    for (int i = 0; i < 32; i++) {
        const uint32_t Abi = smb + (uint32_t)(i & 3) * (GSTW*4);
        LOAD_FRAGS(1, Abi, 1);
        if (i + 2 < 32) G_ISSUE(i + 2);
        CP_COMMIT();
        MMA_SET(0);
        if (i + 1 < 32) {
            CP_WAIT1();
            __syncthreads();
            const uint32_t Abn = smb + (uint32_t)((i+1) & 3) * (GSTW*4);
            LOAD_FRAGS(0, Abn, 0);
        }
        MMA_SET(1);
    }
    #undef G_ISSUE
    #undef LOAD_FRAGS
    #undef MMA_SET

    // epilogue
    const float* bias = (which == 0) ? bq_ : (which == 1) ? bk_ :
                        (which == 2) ? bv_ : bq_;   // mode 3 passes bo in bq_
    const float sc = (which == 0) ? 0.125f * 1.4426950408889634f : 1.f;

    #pragma unroll
    for (int mt = 0; mt < 4; mt++) {
        #pragma unroll
        for (int nt = 0; nt < 4; nt++) {
            const int col = bn + warp_n + nt*8 + tig*2;
            const int lc  = col & 1023;
            const float b0 = bias[lc];
            const float b1 = bias[lc + 1];
            #pragma unroll
            for (int half_ = 0; half_ < 2; half_++) {
                const int m = bm + warp_m + mt*16 + gid + half_*8;
                float vx = (acc[mt][nt][half_*2 + 0] + b0) * sc;
                float vy = (acc[mt][nt][half_*2 + 1] + b1) * sc;
                if (which == 3) {
                    *(float2*)&Oext[(size_t)m * DD + lc] = make_float2(vx, vy);
                } else if (which == 0) {
                    const int bb = m >> 11;
                    const int ll = m & (LL - 1);
                    const int h  = lc >> 6;
                    const int c  = lc & (DH - 1);
                    *(uint32_t*)&g_q[(((size_t)(bb*HH + h)*LL) + ll)*DH + c] =
                        pack2(vx, vy);
                } else {   // K/V: m is the compact row within batch
                    const int h  = lc >> 6;
                    const int c  = lc & (DH - 1);
                    if (which == 2) {   // V transposed+compacted (B,H,dh,Lc)
                        const size_t base = ((size_t)(batch*HH + h)) * DH * LL;
                        g_v[base + (size_t)c    *LL + m] = __float2half_rn(vx);
                        g_v[base + (size_t)(c+1)*LL + m] = __float2half_rn(vy);
                    } else {            // K compacted
                        *(uint32_t*)&g_k[(((size_t)(batch*HH + h)*LL) + m)*DH + c] =
                            pack2(vx, vy);
                    }
                }
            }
        }
    }
}

// ---------------------------------------------------------------------------
// fp16 flash attention on COMPACTED keys (R15-best, unchanged).
// ---------------------------------------------------------------------------
#define AQ_OFF 0
#define AK_OFF (128*36)
#define AV_OFF (AK_OFF + 4*64*36)
#define ATTN_SMEM ((AV_OFF + 4*64*36)*4)

__global__ void __launch_bounds__(256, 2) attn_f16()
{
    extern __shared__ uint32_t sm[];

    const int qt  = blockIdx.x;
    const int h   = blockIdx.y;
    const int b   = blockIdx.z;
    const int tid = threadIdx.x;
    const int wid = tid >> 5;
    const int lane = tid & 31;
    const int gid = lane >> 2;
    const int tig = lane & 3;
    const int m0  = wid * 16;

    const __half* qb = g_q + ((size_t)(b*HH + h))*LL*DH + (size_t)qt*128*DH;
    const __half* kb = g_k + ((size_t)(b*HH + h))*LL*DH;
    const __half* vb = g_v + ((size_t)(b*HH + h))*DH*LL;
    const uint32_t smb = smem_u32(sm);

    const int cnt = g_cnt[b];
    const int nkt = (cnt + 63) >> 6;

    const int g  = lane >> 3;
    const int rr = lane & 7;
    const int a_row = (g & 1) * 8 + rr;
    const int a_kw  = (g >> 1) * 4;
    const int b_row = (g >> 1) * 8 + rr;
    const int b_kw  = (g & 1) * 4;

    #define A_ISSUE(kt_) do { \
        const int tb_ = (kt_) & 3; \
        const __half* ksrc_ = kb + (size_t)(kt_)*64*DH; \
        _Pragma("unroll") \
        for (int rep_ = 0; rep_ < 2; rep_++) { \
            int idx_ = rep_*256 + tid; \
            int r_ = idx_ >> 3, w_ = (idx_ & 7); \
            cp16(smb + (uint32_t)(AK_OFF + tb_*64*36 + r_*36 + w_*4)*4, \
                 ksrc_ + (size_t)r_*DH + w_*8); \
            cp16(smb + (uint32_t)(AV_OFF + tb_*64*36 + r_*36 + w_*4)*4, \
                 vb + (size_t)r_*LL + (kt_)*64 + w_*8); \
        } \
    } while (0)

    #pragma unroll
    for (int rep = 0; rep < 4; rep++) {
        int idx = rep*256 + tid;
        int r = idx >> 3, w = idx & 7;
        cp16(smb + (uint32_t)(AQ_OFF + r*36 + w*4)*4, qb + (size_t)r*DH + w*8);
    }
    A_ISSUE(0);
    CP_COMMIT();
    A_ISSUE(1);
    CP_COMMIT();

    float accO[8][4];
    #pragma unroll
    for (int nt = 0; nt < 8; nt++)
        #pragma unroll
        for (int r = 0; r < 4; r++) accO[nt][r] = 0.f;
    float mi[2] = {-INFINITY, -INFINITY};
    float li[2] = {0.f, 0.f};

    uint32_t qf[4][4];

    for (int kt = 0; kt < nkt; kt++) {
        const int tb = kt & 3;

        if (kt + 2 < nkt) A_ISSUE(kt + 2);
        CP_COMMIT();
        CP_WAIT2();
        __syncthreads();

        if (kt == 0) {
            const uint32_t Qb = smb + (uint32_t)(AQ_OFF + (m0 + a_row)*36)*4;
            #pragma unroll
            for (int ks = 0; ks < 4; ks++)
                ldsm_x4(qf[ks], Qb + (uint32_t)(ks*8 + a_kw)*4);
        }

        float s[8][4];
        #pragma unroll
        for (int nt = 0; nt < 8; nt++)
            #pragma unroll
            for (int r = 0; r < 4; r++) s[nt][r] = 0.f;

        const uint32_t Kb = smb + (uint32_t)(AK_OFF + tb*64*36)*4;
        #pragma unroll
        for (int ks = 0; ks < 4; ks++) {
            const int kb8 = ks * 8;
            #pragma unroll
            for (int j = 0; j < 4; j++) {
                uint32_t bf[4];
                ldsm_x4(bf, Kb + (uint32_t)((j*16 + b_row)*36 + kb8 + b_kw)*4);
                mma_f16(s[2*j],   qf[ks], bf[0], bf[1]);
                mma_f16(s[2*j+1], qf[ks], bf[2], bf[3]);
            }
        }

        // positional tail mask
        #pragma unroll
        for (int nt = 0; nt < 8; nt++) {
            const int c0 = kt*64 + nt*8 + tig*2;
            if (c0     >= cnt) { s[nt][0] = -1e9f; s[nt][2] = -1e9f; }
            if (c0 + 1 >= cnt) { s[nt][1] = -1e9f; s[nt][3] = -1e9f; }
        }

        // online softmax in log2 domain
        #pragma unroll
        for (int half_ = 0; half_ < 2; half_++) {
            float rm = -INFINITY;
            #pragma unroll
            for (int nt = 0; nt < 8; nt++)
                rm = fmaxf(rm, fmaxf(s[nt][half_*2], s[nt][half_*2+1]));
            rm = fmaxf(rm, __shfl_xor_sync(0xffffffffu, rm, 1));
            rm = fmaxf(rm, __shfl_xor_sync(0xffffffffu, rm, 2));
            const float newm = fmaxf(mi[half_], rm);
            const float corr = ex2(mi[half_] - newm);
            float rs = 0.f;
            #pragma unroll
            for (int nt = 0; nt < 8; nt++) {
                s[nt][half_*2]   = ex2(s[nt][half_*2]   - newm);
                s[nt][half_*2+1] = ex2(s[nt][half_*2+1] - newm);
                rs += s[nt][half_*2] + s[nt][half_*2+1];
            }
            rs += __shfl_xor_sync(0xffffffffu, rs, 1);
            rs += __shfl_xor_sync(0xffffffffu, rs, 2);
            li[half_] = li[half_] * corr + rs;
            mi[half_] = newm;
            #pragma unroll
            for (int nt = 0; nt < 8; nt++) {
                accO[nt][half_*2]   *= corr;
                accO[nt][half_*2+1] *= corr;
            }
        }

        // O += P @ V
        const uint32_t Vb = smb + (uint32_t)(AV_OFF + tb*64*36)*4;
        #pragma unroll
        for (int ks = 0; ks < 4; ks++) {
            const int kb8 = ks * 8;
            uint32_t af[4];
            af[0] = pack2(s[2*ks  ][0], s[2*ks  ][1]);
            af[1] = pack2(s[2*ks  ][2], s[2*ks  ][3]);
            af[2] = pack2(s[2*ks+1][0], s[2*ks+1][1]);
            af[3] = pack2(s[2*ks+1][2], s[2*ks+1][3]);
            #pragma unroll
            for (int j = 0; j < 4; j++) {
                uint32_t bf[4];
                ldsm_x4(bf, Vb + (uint32_t)((j*16 + b_row)*36 + kb8 + b_kw)*4);
                mma_f16(accO[2*j],   af, bf[0], bf[1]);
                mma_f16(accO[2*j+1], af, bf[2], bf[3]);
            }
        }
    }
    #undef A_ISSUE

    const float inv0 = 1.f / li[0];
    const float inv1 = 1.f / li[1];
    const int r0 = qt*128 + m0 + gid;
    const int r1 = r0 + 8;
    #pragma unroll
    for (int nt = 0; nt < 8; nt++) {
        const int c = h*DH + nt*8 + tig*2;
        *(uint32_t*)&g_ctx[((size_t)(b*LL + r0))*DD + c] =
            pack2(accO[nt][0]*inv0, accO[nt][1]*inv0);
        *(uint32_t*)&g_ctx[((size_t)(b*LL + r1))*DD + c] =
            pack2(accO[nt][2]*inv1, accO[nt][3]*inv1);
    }
}

// ---------------------------------------------------------------------------
extern "C" void kernel_launch(void* const* d_in, const int* in_sizes, int n_in,
                              void* d_out, int out_size)
{
    const float* x  = (const float*)d_in[0];
    const int* mask = (const int*)d_in[1];
    const float* wq = (const float*)d_in[2];
    const float* bq = (const float*)d_in[3];
    const float* wk = (const float*)d_in[4];
    const float* bk = (const float*)d_in[5];
    const float* wv = (const float*)d_in[6];
    const float* bv = (const float*)d_in[7];
    const float* wo = (const float*)d_in[8];
    const float* bo = (const float*)d_in[9];
    float* out = (float*)d_out;

    cudaFuncSetAttribute(gemm_f16, cudaFuncAttributeMaxDynamicSharedMemorySize,
                         GEMM_SMEM);
    cudaFuncSetAttribute(attn_f16, cudaFuncAttributeMaxDynamicSharedMemorySize,
                         ATTN_SMEM);

    scan_kernel<<<BB, 256>>>(mask);

    const int ncvt = (int)(((size_t)MM*DD/4 + (size_t)DD*DD + 255) / 256);
    cvt_kernel<<<ncvt, 256>>>(x, wq, wk, wv, wo);

    // merged Q + KV projections: 512 Q blocks + 1024 KV blocks (1D grid)
    gemm_f16<<<1536, 256, GEMM_SMEM>>>(bq, bk, bv, nullptr, 0);

    dim3 ga(LL/128, HH, BB);       // 16 x 16 x 4
    attn_f16<<<ga, 256, ATTN_SMEM>>>();

    dim3 go(DD/128, MM/128);       // 8 x 64
    gemm_f16<<<go, 256, GEMM_SMEM>>>(bo, nullptr, nullptr, out, 3);
}